// round 9
// baseline (speedup 1.0000x reference)
#include <cuda_runtime.h>
#include <cstdint>

#define LSEQ  65536
#define HEADS 8
#define DIM   32
#define BS    128
#define NB    (LSEQ / BS)

#define STRIDE      36                       // floats per row, all tiles
#define TILE_FLOATS (3 * 128 * STRIDE)       // Q + K + V per tile
#define SMEM_FLOATS (2 * TILE_FLOATS)
#define SMEM_BYTES  (SMEM_FLOATS * 4)        // 110592 B

// 1/sqrt(32) * log2(e): applied inside the softmax via FFMA
#define SCALE_LOG2E ((float)(0.17677669529663687 * 1.4426950408889634))

__device__ __forceinline__ float ex2(float x) {
    float r;
    asm("ex2.approx.ftz.f32 %0, %1;" : "=f"(r) : "f"(x));
    return r;
}

__device__ __forceinline__ uint32_t f2tf(float x) {
    uint32_t u;
    asm("cvt.rna.tf32.f32 %0, %1;" : "=r"(u) : "f"(x));
    return u;
}

__device__ __forceinline__ void cp16(uint32_t dst, const float* src) {
    asm volatile("cp.async.cg.shared.global [%0], [%1], 16;"
                 :: "r"(dst), "l"(src) : "memory");
}

__device__ __forceinline__ void mma_tf32(float* d,
                                         uint32_t a0, uint32_t a1, uint32_t a2, uint32_t a3,
                                         uint32_t b0, uint32_t b1) {
    asm volatile("mma.sync.aligned.m16n8k8.row.col.f32.tf32.tf32.f32 "
                 "{%0,%1,%2,%3}, {%4,%5,%6,%7}, {%8,%9}, {%0,%1,%2,%3};"
                 : "+f"(d[0]), "+f"(d[1]), "+f"(d[2]), "+f"(d[3])
                 : "r"(a0), "r"(a1), "r"(a2), "r"(a3), "r"(b0), "r"(b1));
}

// ---- stage one (bucket, head) tile via cp.async: 12 x 16B per thread ----
__device__ __forceinline__ void stage_tile(uint32_t sbuf, const float* Qg,
                                           const float* Kg, const float* Vg, int tid) {
    const uint32_t sQ = sbuf;
    const uint32_t sK = sbuf + 128 * STRIDE * 4;
    const uint32_t sV = sbuf + 2 * 128 * STRIDE * 4;
    #pragma unroll
    for (int it = 0; it < 4; it++) {
        int idx = tid + it * 256;            // 0..1023
        int row = idx >> 3, c4 = idx & 7;
        size_t goff = (size_t)row * (HEADS * DIM) + c4 * 4;    // floats
        uint32_t soff = (uint32_t)(row * STRIDE + c4 * 4) * 4; // bytes (16-aligned)
        cp16(sQ + soff, Qg + goff);
        cp16(sK + soff, Kg + goff);
        cp16(sV + soff, Vg + goff);
    }
}

// ---- in-place fp32 -> tf32(RNA) conversion of a landed tile ----
__device__ __forceinline__ void convert_tile(float* buf, int tid) {
    #pragma unroll
    for (int it = 0; it < 12; it++) {
        int idx = tid + it * 256;            // 0..3071 (3 arrays x 128 rows x 8 chunks)
        int arr = idx >> 10;                 // 0=Q, 1=K, 2=V
        int rem = idx & 1023;
        int row = rem >> 3, c4 = rem & 7;
        float* p = buf + arr * 128 * STRIDE + row * STRIDE + c4 * 4;
        float4 v = *(const float4*)p;
        uint4 t = make_uint4(f2tf(v.x), f2tf(v.y), f2tf(v.z), f2tf(v.w));
        *(uint4*)p = t;
    }
}

// ---- full compute for one tile (sync-free inside) ----
__device__ __forceinline__ void compute_tile(const float* Qs, const float* Ks,
                                             const float* Vs, float* __restrict__ O,
                                             size_t base, int lo, int hi, bool full,
                                             int gid, int tig, int r0) {
    // ---- QK^T : scores[16 rows][128 cols] (raw, unscaled; operands tf32-RNA) ----
    float sacc[16][4];
    #pragma unroll
    for (int ct = 0; ct < 16; ct++)
        #pragma unroll
        for (int j = 0; j < 4; j++) sacc[ct][j] = 0.f;

    #pragma unroll
    for (int ks = 0; ks < 4; ks++) {
        int kc = ks * 8 + 2 * tig;
        float2 alo = *(const float2*)(Qs + r0 * STRIDE + kc);        // (a0, a2)
        float2 ahi = *(const float2*)(Qs + (r0 + 8) * STRIDE + kc);  // (a1, a3)
        uint32_t a0 = __float_as_uint(alo.x), a2 = __float_as_uint(alo.y);
        uint32_t a1 = __float_as_uint(ahi.x), a3 = __float_as_uint(ahi.y);
        #pragma unroll
        for (int ct = 0; ct < 16; ct++) {
            float2 bp = *(const float2*)(Ks + (ct * 8 + gid) * STRIDE + kc);  // (b0, b1)
            mma_tf32(sacc[ct], a0, a1, a2, a3,
                     __float_as_uint(bp.x), __float_as_uint(bp.y));
        }
    }

    // ---- softmax: raw max, then e = ex2(fma(S, C, -M*C)) ----
    float m0 = -1e30f, m1 = -1e30f;
    if (full) {
        #pragma unroll
        for (int ct = 0; ct < 16; ct++) {
            m0 = fmaxf(m0, fmaxf(sacc[ct][0], sacc[ct][1]));
            m1 = fmaxf(m1, fmaxf(sacc[ct][2], sacc[ct][3]));
        }
    } else {
        #pragma unroll
        for (int ct = 0; ct < 16; ct++) {
            int c = ct * 8 + 2 * tig;
            bool v0 = (c >= lo) && (c < hi);
            bool v1 = (c + 1 >= lo) && (c + 1 < hi);
            if (v0) { m0 = fmaxf(m0, sacc[ct][0]); m1 = fmaxf(m1, sacc[ct][2]); }
            if (v1) { m0 = fmaxf(m0, sacc[ct][1]); m1 = fmaxf(m1, sacc[ct][3]); }
        }
    }
    m0 = fmaxf(m0, __shfl_xor_sync(0xffffffffu, m0, 1));
    m0 = fmaxf(m0, __shfl_xor_sync(0xffffffffu, m0, 2));
    m1 = fmaxf(m1, __shfl_xor_sync(0xffffffffu, m1, 1));
    m1 = fmaxf(m1, __shfl_xor_sync(0xffffffffu, m1, 2));

    const float C = SCALE_LOG2E;
    const float nmc0 = -m0 * C, nmc1 = -m1 * C;

    float l0 = 0.f, l1 = 0.f;
    if (full) {
        #pragma unroll
        for (int ct = 0; ct < 16; ct++) {
            float e0 = ex2(__fmaf_rn(sacc[ct][0], C, nmc0));
            float e1 = ex2(__fmaf_rn(sacc[ct][1], C, nmc0));
            float e2 = ex2(__fmaf_rn(sacc[ct][2], C, nmc1));
            float e3 = ex2(__fmaf_rn(sacc[ct][3], C, nmc1));
            l0 += e0 + e1;
            l1 += e2 + e3;
            sacc[ct][0] = __uint_as_float(f2tf(e0));
            sacc[ct][1] = __uint_as_float(f2tf(e1));
            sacc[ct][2] = __uint_as_float(f2tf(e2));
            sacc[ct][3] = __uint_as_float(f2tf(e3));
        }
    } else {
        #pragma unroll
        for (int ct = 0; ct < 16; ct++) {
            int c = ct * 8 + 2 * tig;
            bool v0 = (c >= lo) && (c < hi);
            bool v1 = (c + 1 >= lo) && (c + 1 < hi);
            float e0 = v0 ? ex2(__fmaf_rn(sacc[ct][0], C, nmc0)) : 0.f;
            float e1 = v1 ? ex2(__fmaf_rn(sacc[ct][1], C, nmc0)) : 0.f;
            float e2 = v0 ? ex2(__fmaf_rn(sacc[ct][2], C, nmc1)) : 0.f;
            float e3 = v1 ? ex2(__fmaf_rn(sacc[ct][3], C, nmc1)) : 0.f;
            l0 += e0 + e1;
            l1 += e2 + e3;
            sacc[ct][0] = __uint_as_float(f2tf(e0));
            sacc[ct][1] = __uint_as_float(f2tf(e1));
            sacc[ct][2] = __uint_as_float(f2tf(e2));
            sacc[ct][3] = __uint_as_float(f2tf(e3));
        }
    }
    l0 += __shfl_xor_sync(0xffffffffu, l0, 1);
    l0 += __shfl_xor_sync(0xffffffffu, l0, 2);
    l1 += __shfl_xor_sync(0xffffffffu, l1, 1);
    l1 += __shfl_xor_sync(0xffffffffu, l1, 2);

    // ---- P @ V, P in registers (C->A layout via k-permutation on V rows) ----
    float oacc[4][4];
    #pragma unroll
    for (int nt = 0; nt < 4; nt++)
        #pragma unroll
        for (int j = 0; j < 4; j++) oacc[nt][j] = 0.f;

    #pragma unroll
    for (int kt = 0; kt < 16; kt++) {
        int key0 = kt * 8 + 2 * tig;
        uint32_t a0 = __float_as_uint(sacc[kt][0]);
        uint32_t a1 = __float_as_uint(sacc[kt][2]);
        uint32_t a2 = __float_as_uint(sacc[kt][1]);
        uint32_t a3 = __float_as_uint(sacc[kt][3]);
        const float* v0p = Vs + key0 * STRIDE + gid;
        const float* v1p = v0p + STRIDE;
        #pragma unroll
        for (int nt = 0; nt < 4; nt++) {
            uint32_t b0 = __float_as_uint(v0p[nt * 8]);
            uint32_t b1 = __float_as_uint(v1p[nt * 8]);
            mma_tf32(oacc[nt], a0, a1, a2, a3, b0, b1);
        }
    }

    // ---- normalize, mask invalid queries, write out ----
    float s0 = ((r0 >= lo) && (r0 < hi) && l0 > 0.f)         ? __frcp_rn(l0) : 0.f;
    float s1 = ((r0 + 8 >= lo) && (r0 + 8 < hi) && l1 > 0.f) ? __frcp_rn(l1) : 0.f;
    float* O0 = O + base + (size_t)r0 * (HEADS * DIM);
    float* O1 = O + base + (size_t)(r0 + 8) * (HEADS * DIM);
    #pragma unroll
    for (int nt = 0; nt < 4; nt++) {
        int c = nt * 8 + 2 * tig;
        *(float2*)(O0 + c) = make_float2(oacc[nt][0] * s0, oacc[nt][1] * s0);
        *(float2*)(O1 + c) = make_float2(oacc[nt][2] * s1, oacc[nt][3] * s1);
    }
}

__global__ void __launch_bounds__(256, 2)
bucket_attn_kernel(const float* __restrict__ Q, const float* __restrict__ K,
                   const float* __restrict__ V, const int* __restrict__ scope,
                   float* __restrict__ O) {
    extern __shared__ float smem[];
    float* buf0 = smem;
    float* buf1 = smem + TILE_FLOATS;

    const int bucket = blockIdx.x;
    const int hp     = blockIdx.y;      // head pair: heads 2hp, 2hp+1
    const int b      = blockIdx.z;
    const int tid    = threadIdx.x;

    const int sidx = (b * NB + bucket) * 2;
    const int lo = scope[sidx]     - bucket * BS;
    const int hi = scope[sidx + 1] - bucket * BS;
    const bool full = (lo <= 0) && (hi >= BS);   // uniform per CTA (same for both heads)

    const size_t base0 = ((size_t)(b * LSEQ + bucket * BS) * HEADS + 2 * hp) * DIM;
    const size_t base1 = base0 + DIM;

    const uint32_t sb0 = (uint32_t)__cvta_generic_to_shared(buf0);
    const uint32_t sb1 = (uint32_t)__cvta_generic_to_shared(buf1);

    // ---- prefetch both tiles via cp.async ----
    stage_tile(sb0, Q + base0, K + base0, V + base0, tid);
    asm volatile("cp.async.commit_group;" ::: "memory");
    stage_tile(sb1, Q + base1, K + base1, V + base1, tid);
    asm volatile("cp.async.commit_group;" ::: "memory");

    const int lane = tid & 31;
    const int w    = tid >> 5;
    const int gid  = lane >> 2;
    const int tig  = lane & 3;
    const int r0   = w * 16 + gid;

    // ---- tile 0 (tile 1's loads stream in behind conversion + compute) ----
    asm volatile("cp.async.wait_group 1;" ::: "memory");
    __syncthreads();
    convert_tile(buf0, tid);
    __syncthreads();
    compute_tile(buf0, buf0 + 128 * STRIDE, buf0 + 2 * 128 * STRIDE,
                 O, base0, lo, hi, full, gid, tig, r0);

    // ---- tile 1 ----
    asm volatile("cp.async.wait_group 0;" ::: "memory");
    __syncthreads();
    convert_tile(buf1, tid);
    __syncthreads();
    compute_tile(buf1, buf1 + 128 * STRIDE, buf1 + 2 * 128 * STRIDE,
                 O, base1, lo, hi, full, gid, tig, r0);
}

extern "C" void kernel_launch(void* const* d_in, const int* in_sizes, int n_in,
                              void* d_out, int out_size) {
    const float* Q     = (const float*)d_in[0];
    const float* K     = (const float*)d_in[1];
    const float* V     = (const float*)d_in[2];
    const int*   scope = (const int*)d_in[3];
    (void)n_in; (void)out_size;

    int B = in_sizes[0] / (LSEQ * HEADS * DIM);  // = 2

    cudaFuncSetAttribute(bucket_attn_kernel,
                         cudaFuncAttributeMaxDynamicSharedMemorySize, SMEM_BYTES);
    cudaFuncSetAttribute(bucket_attn_kernel,
                         cudaFuncAttributePreferredSharedMemoryCarveout, 100);

    dim3 grid(NB, HEADS / 2, B);
    bucket_attn_kernel<<<grid, 256, SMEM_BYTES>>>(Q, K, V, scope, (float*)d_out);
}

// round 10
// speedup vs baseline: 1.4085x; 1.4085x over previous
#include <cuda_runtime.h>
#include <cstdint>

#define LSEQ  65536
#define HEADS 8
#define DIM   32
#define BS    128
#define NB    (LSEQ / BS)

#define QK_STRIDE 40   // floats; float2 fragment loads at full crossbar rate
#define V_STRIDE  36   // floats; scalar PV B-loads conflict-free
#define SMEM_FLOATS (2 * 128 * QK_STRIDE + 128 * V_STRIDE)
#define SMEM_BYTES  (SMEM_FLOATS * 4)

// 1/sqrt(32) * log2(e): QK scores come out in the exp2 domain
#define SCALE_LOG2E ((float)(0.17677669529663687 * 1.4426950408889634))

// compensation for HW truncation (RZ) of P and V operands at the PV MMA:
// each op shrinks magnitude by ~0.5 * 2^-10 * ln2 ~= 3.38e-4 on average
#define TRUNC_COMP 1.000676f

__device__ __forceinline__ uint32_t f2tf(float x) {
    uint32_t u;
    asm("cvt.rna.tf32.f32 %0, %1;" : "=r"(u) : "f"(x));
    return u;
}

__device__ __forceinline__ float ex2(float x) {
    float r;
    asm("ex2.approx.ftz.f32 %0, %1;" : "=f"(r) : "f"(x));
    return r;
}

__device__ __forceinline__ void cp16(uint32_t dst, const float* src) {
    asm volatile("cp.async.cg.shared.global [%0], [%1], 16;"
                 :: "r"(dst), "l"(src) : "memory");
}

__device__ __forceinline__ void mma_tf32(float* d,
                                         uint32_t a0, uint32_t a1, uint32_t a2, uint32_t a3,
                                         uint32_t b0, uint32_t b1) {
    asm volatile("mma.sync.aligned.m16n8k8.row.col.f32.tf32.tf32.f32 "
                 "{%0,%1,%2,%3}, {%4,%5,%6,%7}, {%8,%9}, {%0,%1,%2,%3};"
                 : "+f"(d[0]), "+f"(d[1]), "+f"(d[2]), "+f"(d[3])
                 : "r"(a0), "r"(a1), "r"(a2), "r"(a3), "r"(b0), "r"(b1));
}

__global__ void __launch_bounds__(256, 2)
bucket_attn_kernel(const float* __restrict__ Q, const float* __restrict__ K,
                   const float* __restrict__ V, const int* __restrict__ scope,
                   float* __restrict__ O) {
    extern __shared__ float smem[];
    float* Qs = smem;                       // [128][40]  tf32-RNA
    float* Ks = Qs + 128 * QK_STRIDE;       // [128][40]  tf32-RNA
    float* Vs = Ks + 128 * QK_STRIDE;       // [128][36]  raw fp32 (HW-truncated at MMA)

    const int bucket = blockIdx.x;
    const int h      = blockIdx.y;
    const int b      = blockIdx.z;
    const int tid    = threadIdx.x;

    const int sidx = (b * NB + bucket) * 2;
    const int lo = scope[sidx]     - bucket * BS;
    const int hi = scope[sidx + 1] - bucket * BS;
    const bool full = (lo <= 0) && (hi >= BS);   // uniform per CTA

    const size_t base = ((size_t)(b * LSEQ + bucket * BS) * HEADS + h) * DIM;
    const float4* Qg = (const float4*)(Q + base);
    const float4* Kg = (const float4*)(K + base);
    const float*  Vg = V + base;
    const int rs4 = HEADS * DIM / 4;  // 64 float4 between rows

    // ---- V prefetch via cp.async (raw fp32), issued before the Q/K LDG block ----
    {
        const uint32_t sV = (uint32_t)__cvta_generic_to_shared(Vs);
        #pragma unroll
        for (int it = 0; it < 4; it++) {
            int idx = tid + it * 256;
            int row = idx >> 3, c4 = idx & 7;
            cp16(sV + (uint32_t)(row * V_STRIDE + c4 * 4) * 4,
                 Vg + (size_t)row * (HEADS * DIM) + c4 * 4);
        }
        asm volatile("cp.async.commit_group;" ::: "memory");
    }

    // ---- Stage Q,K into SMEM (tf32-RNA; Q pre-scaled into exp2 domain) ----
    #pragma unroll
    for (int it = 0; it < 4; it++) {
        int idx = tid + it * 256;        // 0..1023 (128 rows x 8 float4)
        int row = idx >> 3, c4 = idx & 7;
        float4 q = Qg[row * rs4 + c4];
        float4 k = Kg[row * rs4 + c4];
        uint4 qt = make_uint4(f2tf(q.x * SCALE_LOG2E), f2tf(q.y * SCALE_LOG2E),
                              f2tf(q.z * SCALE_LOG2E), f2tf(q.w * SCALE_LOG2E));
        uint4 kt = make_uint4(f2tf(k.x), f2tf(k.y), f2tf(k.z), f2tf(k.w));
        *(uint4*)(Qs + row * QK_STRIDE + c4 * 4) = qt;
        *(uint4*)(Ks + row * QK_STRIDE + c4 * 4) = kt;
    }
    asm volatile("cp.async.wait_group 0;" ::: "memory");
    __syncthreads();

    const int lane = tid & 31;
    const int w    = tid >> 5;
    const int gid  = lane >> 2;     // 0..7
    const int tig  = lane & 3;      // 0..3
    const int r0   = w * 16 + gid;  // this lane's rows: r0 and r0+8

    // ---- QK^T : scores[16 rows][128 cols], per-warp (k-permuted operands) ----
    float sacc[16][4];
    #pragma unroll
    for (int ct = 0; ct < 16; ct++)
        #pragma unroll
        for (int j = 0; j < 4; j++) sacc[ct][j] = 0.f;

    #pragma unroll
    for (int ks = 0; ks < 4; ks++) {
        int kc = ks * 8 + 2 * tig;
        float2 alo = *(const float2*)(Qs + r0 * QK_STRIDE + kc);        // (a0, a2)
        float2 ahi = *(const float2*)(Qs + (r0 + 8) * QK_STRIDE + kc);  // (a1, a3)
        uint32_t a0 = __float_as_uint(alo.x), a2 = __float_as_uint(alo.y);
        uint32_t a1 = __float_as_uint(ahi.x), a3 = __float_as_uint(ahi.y);
        #pragma unroll
        for (int ct = 0; ct < 16; ct++) {
            float2 bp = *(const float2*)(Ks + (ct * 8 + gid) * QK_STRIDE + kc);  // (b0, b1)
            mma_tf32(sacc[ct], a0, a1, a2, a3,
                     __float_as_uint(bp.x), __float_as_uint(bp.y));
        }
    }

    // ---- softmax in exp2 domain (quad shuffles; unnormalized; exact fp32 sums) ----
    float m0 = -1e30f, m1 = -1e30f;
    if (full) {
        #pragma unroll
        for (int ct = 0; ct < 16; ct++) {
            m0 = fmaxf(m0, fmaxf(sacc[ct][0], sacc[ct][1]));
            m1 = fmaxf(m1, fmaxf(sacc[ct][2], sacc[ct][3]));
        }
    } else {
        #pragma unroll
        for (int ct = 0; ct < 16; ct++) {
            int c = ct * 8 + 2 * tig;
            bool v0 = (c >= lo) && (c < hi);
            bool v1 = (c + 1 >= lo) && (c + 1 < hi);
            if (v0) { m0 = fmaxf(m0, sacc[ct][0]); m1 = fmaxf(m1, sacc[ct][2]); }
            if (v1) { m0 = fmaxf(m0, sacc[ct][1]); m1 = fmaxf(m1, sacc[ct][3]); }
        }
    }
    m0 = fmaxf(m0, __shfl_xor_sync(0xffffffffu, m0, 1));
    m0 = fmaxf(m0, __shfl_xor_sync(0xffffffffu, m0, 2));
    m1 = fmaxf(m1, __shfl_xor_sync(0xffffffffu, m1, 1));
    m1 = fmaxf(m1, __shfl_xor_sync(0xffffffffu, m1, 2));

    float l0 = 0.f, l1 = 0.f;
    if (full) {
        #pragma unroll
        for (int ct = 0; ct < 16; ct++) {
            float e0 = ex2(sacc[ct][0] - m0);
            float e1 = ex2(sacc[ct][1] - m0);
            float e2 = ex2(sacc[ct][2] - m1);
            float e3 = ex2(sacc[ct][3] - m1);
            l0 += e0 + e1;
            l1 += e2 + e3;
            sacc[ct][0] = e0; sacc[ct][1] = e1;   // raw fp32 P; HW truncates at MMA
            sacc[ct][2] = e2; sacc[ct][3] = e3;
        }
    } else {
        #pragma unroll
        for (int ct = 0; ct < 16; ct++) {
            int c = ct * 8 + 2 * tig;
            bool v0 = (c >= lo) && (c < hi);
            bool v1 = (c + 1 >= lo) && (c + 1 < hi);
            float e0 = v0 ? ex2(sacc[ct][0] - m0) : 0.f;
            float e1 = v1 ? ex2(sacc[ct][1] - m0) : 0.f;
            float e2 = v0 ? ex2(sacc[ct][2] - m1) : 0.f;
            float e3 = v1 ? ex2(sacc[ct][3] - m1) : 0.f;
            l0 += e0 + e1;
            l1 += e2 + e3;
            sacc[ct][0] = e0; sacc[ct][1] = e1;
            sacc[ct][2] = e2; sacc[ct][3] = e3;
        }
    }
    l0 += __shfl_xor_sync(0xffffffffu, l0, 1);
    l0 += __shfl_xor_sync(0xffffffffu, l0, 2);
    l1 += __shfl_xor_sync(0xffffffffu, l1, 1);
    l1 += __shfl_xor_sync(0xffffffffu, l1, 2);

    // ---- P @ V, P in registers (C->A layout via k-permutation on V rows) ----
    float oacc[4][4];
    #pragma unroll
    for (int nt = 0; nt < 4; nt++)
        #pragma unroll
        for (int j = 0; j < 4; j++) oacc[nt][j] = 0.f;

    #pragma unroll
    for (int kt = 0; kt < 16; kt++) {
        int key0 = kt * 8 + 2 * tig;
        uint32_t a0 = __float_as_uint(sacc[kt][0]);
        uint32_t a1 = __float_as_uint(sacc[kt][2]);
        uint32_t a2 = __float_as_uint(sacc[kt][1]);
        uint32_t a3 = __float_as_uint(sacc[kt][3]);
        const float* v0p = Vs + key0 * V_STRIDE + gid;
        const float* v1p = v0p + V_STRIDE;
        #pragma unroll
        for (int nt = 0; nt < 4; nt++) {
            uint32_t b0 = __float_as_uint(v0p[nt * 8]);
            uint32_t b1 = __float_as_uint(v1p[nt * 8]);
            mma_tf32(oacc[nt], a0, a1, a2, a3, b0, b1);
        }
    }

    // ---- normalize (with truncation-bias compensation), mask, write out ----
    float s0 = ((r0 >= lo) && (r0 < hi) && l0 > 0.f)
                   ? __frcp_rn(l0) * TRUNC_COMP : 0.f;
    float s1 = ((r0 + 8 >= lo) && (r0 + 8 < hi) && l1 > 0.f)
                   ? __frcp_rn(l1) * TRUNC_COMP : 0.f;
    float* O0 = O + base + (size_t)r0 * (HEADS * DIM);
    float* O1 = O + base + (size_t)(r0 + 8) * (HEADS * DIM);
    #pragma unroll
    for (int nt = 0; nt < 4; nt++) {
        int c = nt * 8 + 2 * tig;
        *(float2*)(O0 + c) = make_float2(oacc[nt][0] * s0, oacc[nt][1] * s0);
        *(float2*)(O1 + c) = make_float2(oacc[nt][2] * s1, oacc[nt][3] * s1);
    }
}

extern "C" void kernel_launch(void* const* d_in, const int* in_sizes, int n_in,
                              void* d_out, int out_size) {
    const float* Q     = (const float*)d_in[0];
    const float* K     = (const float*)d_in[1];
    const float* V     = (const float*)d_in[2];
    const int*   scope = (const int*)d_in[3];
    (void)n_in; (void)out_size;

    int B = in_sizes[0] / (LSEQ * HEADS * DIM);  // = 2

    cudaFuncSetAttribute(bucket_attn_kernel,
                         cudaFuncAttributeMaxDynamicSharedMemorySize, SMEM_BYTES);

    dim3 grid(NB, HEADS, B);
    bucket_attn_kernel<<<grid, 256, SMEM_BYTES>>>(Q, K, V, scope, (float*)d_out);
}